// round 1
// baseline (speedup 1.0000x reference)
#include <cuda_runtime.h>
#include <math.h>
#include <stdint.h>

#define BHn   96
#define Nn    1024
#define Cc    64
#define RCc   32
#define RNn   128
#define NM1   1023
#define ROWS_TOT (BHn*NM1)   /* 98208 */
#define KTOP  16
#define BUDGET 256

// ---------------- scratch (static device memory; no allocations) ----------------
__device__ __align__(16) float g_qp[BHn*Nn*RCc];        // [bh][n][rc]
__device__ __align__(16) float g_kp[BHn*Nn*RCc];        // [bh][n][rc]
__device__ __align__(16) float g_kp2p[8*BHn*RCc*RNn];   // partial sums over n-chunks
__device__ __align__(16) float g_kp2[BHn*RCc*RNn];      // [bh][rc][rn]
__device__ __align__(16) float g_basis[RNn*Nn];         // [rn][n] thresholded |proj_back^T|
__device__ __align__(16) float g_cval[(size_t)ROWS_TOT*KTOP];
__device__ __align__(16) int   g_cidx[(size_t)ROWS_TOT*KTOP];

// ---------------- basis = Threshold(|proj_back_n.T|) ----------------
__global__ void k_basis(const float* __restrict__ pb) {
    int i = blockIdx.x*256 + threadIdx.x;          // i = j*128 + c  (coalesced read)
    if (i < RNn*Nn) {
        int j = i >> 7, c = i & 127;
        float v = fabsf(pb[i]);
        g_basis[(size_t)c*Nn + j] = (v > 0.02f) ? v : 0.0f;
    }
}

// ---------------- qp / kp projection: out[row][rc] = x[row]·w[rc] + b[rc] ----------------
// warp holds one w row per lane in registers; 16 rows per warp via shuffles.
__global__ void k_proj(const float* __restrict__ x, const float* __restrict__ w,
                       const float* __restrict__ b, int which) {
    float* out = which ? g_kp : g_qp;
    int warp = threadIdx.x >> 5, lane = threadIdx.x & 31;
    int row0 = (blockIdx.x*8 + warp)*16;
    float wr[64];
    #pragma unroll
    for (int c4 = 0; c4 < 16; c4++) {
        float4 t = *(const float4*)(w + lane*64 + c4*4);
        wr[c4*4+0]=t.x; wr[c4*4+1]=t.y; wr[c4*4+2]=t.z; wr[c4*4+3]=t.w;
    }
    float bias = b[lane];
    for (int r = 0; r < 16; r++) {
        int row = row0 + r;
        float qlo = x[(size_t)row*64 + lane];
        float qhi = x[(size_t)row*64 + 32 + lane];
        float acc = 0.0f;
        #pragma unroll
        for (int c = 0; c < 32; c++) acc = fmaf(__shfl_sync(0xffffffffu, qlo, c), wr[c],    acc);
        #pragma unroll
        for (int c = 0; c < 32; c++) acc = fmaf(__shfl_sync(0xffffffffu, qhi, c), wr[32+c], acc);
        out[(size_t)row*32 + lane] = acc + bias;
    }
}

// ---------------- kp2 partial: per (bh, n-chunk of 128): C[32][128] += kp^T * proj_n ----------------
extern __shared__ float sm_kp2[];
__global__ void k_kp2_part(const float* __restrict__ proj_n) {
    float* kp_s = sm_kp2;             // [128][32]
    float* pj_s = sm_kp2 + 4096;      // [128][128]
    int bh = blockIdx.x, ch = blockIdx.y;
    int n0 = ch*128, tid = threadIdx.x;
    const float4* src = (const float4*)(g_kp + ((size_t)bh*Nn + n0)*32);
    float4* dst = (float4*)kp_s;
    for (int i = tid; i < 1024; i += 256) dst[i] = src[i];
    const float4* ps = (const float4*)(proj_n + (size_t)n0*128);
    float4* pd = (float4*)pj_s;
    for (int i = tid; i < 4096; i += 256) pd[i] = ps[i];
    __syncthreads();
    int rc0 = (tid & 7)*4;
    int rn0 = (tid >> 3)*4;
    float acc[4][4];
    #pragma unroll
    for (int i = 0; i < 4; i++)
        #pragma unroll
        for (int j = 0; j < 4; j++) acc[i][j] = 0.0f;
    #pragma unroll 4
    for (int n = 0; n < 128; n++) {
        float4 a = *(const float4*)(kp_s + n*32 + rc0);
        float4 p = *(const float4*)(pj_s + n*128 + rn0);
        float av[4] = {a.x,a.y,a.z,a.w};
        float pv[4] = {p.x,p.y,p.z,p.w};
        #pragma unroll
        for (int i = 0; i < 4; i++)
            #pragma unroll
            for (int j = 0; j < 4; j++) acc[i][j] = fmaf(av[i], pv[j], acc[i][j]);
    }
    float* outp = g_kp2p + ((size_t)ch*BHn + bh)*4096;
    #pragma unroll
    for (int i = 0; i < 4; i++) {
        float4 o = {acc[i][0], acc[i][1], acc[i][2], acc[i][3]};
        *(float4*)(outp + (rc0+i)*128 + rn0) = o;
    }
}

__global__ void k_kp2_red() {
    int i = blockIdx.x*256 + threadIdx.x;
    if (i < BHn*RCc*RNn) {
        float s = 0.0f;
        #pragma unroll
        for (int ch = 0; ch < 8; ch++) s += g_kp2p[(size_t)ch*BHn*4096 + i];
        g_kp2[i] = s;
    }
}

// ---------------- cheap_attn + softmax + topk16 (one warp per row) ----------------
__global__ void k_cheap(float* __restrict__ out_coef) {
    int warp = threadIdx.x >> 5, lane = threadIdx.x & 31;
    int rr = blockIdx.x*8 + warp;
    if (rr >= ROWS_TOT) return;
    int bh = rr / NM1;
    int n  = rr - bh*NM1 + 1;

    float qv = g_qp[((size_t)bh*Nn + n)*32 + lane];
    const float4* kb = (const float4*)(g_kp2 + (size_t)bh*4096);
    float4 acc = {0.f,0.f,0.f,0.f};
    #pragma unroll
    for (int rc = 0; rc < 32; rc++) {
        float a = __shfl_sync(0xffffffffu, qv, rc);
        float4 kv = __ldg(kb + rc*32 + lane);
        acc.x = fmaf(a, kv.x, acc.x);
        acc.y = fmaf(a, kv.y, acc.y);
        acc.z = fmaf(a, kv.z, acc.z);
        acc.w = fmaf(a, kv.w, acc.w);
    }
    const float scale = 0.28867513459481287f;   // 12^-0.5
    float l[4] = {acc.x*scale, acc.y*scale, acc.z*scale, acc.w*scale};

    float m = fmaxf(fmaxf(l[0], l[1]), fmaxf(l[2], l[3]));
    #pragma unroll
    for (int off = 16; off; off >>= 1) m = fmaxf(m, __shfl_xor_sync(0xffffffffu, m, off));
    float e[4], s = 0.0f;
    #pragma unroll
    for (int j = 0; j < 4; j++) { e[j] = expf(l[j] - m); s += e[j]; }
    #pragma unroll
    for (int off = 16; off; off >>= 1) s += __shfl_xor_sync(0xffffffffu, s, off);
    float c[4];
    #pragma unroll
    for (int j = 0; j < 4; j++) c[j] = e[j] / s;

    // top-16 of 128 (value desc, tie -> lower index, matching jax.lax.top_k)
    unsigned rem = 0xFu, sel = 0u;
    float myv = 0.0f; int myi = 0;
    for (int t = 0; t < 16; t++) {
        float bv = -1.0f; int bi = 0x7fffffff;
        #pragma unroll
        for (int j = 0; j < 4; j++) {
            if (rem & (1u << j)) {
                float v = c[j]; int idx = lane*4 + j;
                if (v > bv || (v == bv && idx < bi)) { bv = v; bi = idx; }
            }
        }
        #pragma unroll
        for (int off = 16; off; off >>= 1) {
            float ov = __shfl_xor_sync(0xffffffffu, bv, off);
            int   oi = __shfl_xor_sync(0xffffffffu, bi, off);
            if (ov > bv || (ov == bv && oi < bi)) { bv = ov; bi = oi; }
        }
        if ((bi >> 2) == lane) { rem &= ~(1u << (bi & 3)); sel |= (1u << (bi & 3)); }
        if (lane == t) { myv = bv; myi = bi; }
    }
    // store compact list sorted by ascending index (mimic reference accumulation order)
    int rank = 0;
    #pragma unroll
    for (int u = 0; u < 16; u++) {
        int oi = __shfl_sync(0xffffffffu, myi, u);
        if (u != lane && oi < myi) rank++;
    }
    if (lane < 16) {
        g_cval[(size_t)rr*16 + rank] = myv;
        g_cidx[(size_t)rr*16 + rank] = myi;
    }
    // dense basis_coef row
    float4 o;
    o.x = (sel & 1u) ? c[0] : 0.0f;
    o.y = (sel & 2u) ? c[1] : 0.0f;
    o.z = (sel & 4u) ? c[2] : 0.0f;
    o.w = (sel & 8u) ? c[3] : 0.0f;
    *(float4*)(out_coef + (size_t)rr*128 + lane*4) = o;
}

// ---------------- fused sparse SpMM (approx_attn) + top-256 radix-select mask ----------------
extern __shared__ float sm_cd[];
__global__ __launch_bounds__(512, 1) void k_spmm_mask(float* __restrict__ out_approx,
                                                      float* __restrict__ out_mask) {
    float* rowbuf = sm_cd;                       // 32 rows x 1024
    int*   histb  = (int*)(sm_cd + 32*1024);     // 16 warps x 256 bins
    int tid = threadIdx.x;
    int row_l = tid >> 4, cg = tid & 15;
    int rr = blockIdx.x*32 + row_l;

    float cv[16]; int ci[16];
    #pragma unroll
    for (int t = 0; t < 16; t++) {
        cv[t] = g_cval[(size_t)rr*16 + t];
        ci[t] = g_cidx[(size_t)rr*16 + t];
    }
    const float4* b4 = (const float4*)g_basis;   // row pitch 256 float4
    float* outp = out_approx + (size_t)rr*1024;
    float4* rb = (float4*)(rowbuf + row_l*1024);

    #pragma unroll
    for (int jt = 0; jt < 4; jt++) {
        float4 a0 = {0,0,0,0}, a1 = {0,0,0,0}, a2 = {0,0,0,0}, a3 = {0,0,0,0};
        #pragma unroll
        for (int t = 0; t < 16; t++) {
            const float4* bp = b4 + (size_t)ci[t]*256 + jt*64 + cg;
            float v = cv[t];
            float4 x0 = __ldg(bp);
            float4 x1 = __ldg(bp + 16);
            float4 x2 = __ldg(bp + 32);
            float4 x3 = __ldg(bp + 48);
            a0.x = fmaf(v, x0.x, a0.x); a0.y = fmaf(v, x0.y, a0.y); a0.z = fmaf(v, x0.z, a0.z); a0.w = fmaf(v, x0.w, a0.w);
            a1.x = fmaf(v, x1.x, a1.x); a1.y = fmaf(v, x1.y, a1.y); a1.z = fmaf(v, x1.z, a1.z); a1.w = fmaf(v, x1.w, a1.w);
            a2.x = fmaf(v, x2.x, a2.x); a2.y = fmaf(v, x2.y, a2.y); a2.z = fmaf(v, x2.z, a2.z); a2.w = fmaf(v, x2.w, a2.w);
            a3.x = fmaf(v, x3.x, a3.x); a3.y = fmaf(v, x3.y, a3.y); a3.z = fmaf(v, x3.z, a3.z); a3.w = fmaf(v, x3.w, a3.w);
        }
        int c4 = jt*64 + cg;
        ((float4*)outp)[c4]      = a0;
        ((float4*)outp)[c4 + 16] = a1;
        ((float4*)outp)[c4 + 32] = a2;
        ((float4*)outp)[c4 + 48] = a3;
        rb[c4]      = a0;
        rb[c4 + 16] = a1;
        rb[c4 + 32] = a2;
        rb[c4 + 48] = a3;
    }
    __syncthreads();

    // selection phase: each warp handles 2 rows
    int warp = tid >> 5, lane = tid & 31;
    int* h = histb + warp*256;
    for (int s = 0; s < 2; s++) {
        int rl = warp*2 + s;
        int rrow = blockIdx.x*32 + rl;
        const float* rv = rowbuf + rl*1024;
        unsigned prefix = 0u; int k = BUDGET;
        #pragma unroll
        for (int pass = 0; pass < 4; pass++) {
            int shift = 24 - pass*8;
            for (int i = lane; i < 256; i += 32) h[i] = 0;
            __syncwarp();
            for (int i = lane; i < 1024; i += 32) {
                unsigned u = __float_as_uint(rv[i]);
                bool match = (pass == 0) || ((u >> (shift + 8)) == (prefix >> (shift + 8)));
                if (match) atomicAdd(&h[(u >> shift) & 255u], 1);
            }
            __syncwarp();
            int loc[8]; int tot = 0;
            #pragma unroll
            for (int b = 0; b < 8; b++) { loc[b] = h[lane*8 + b]; tot += loc[b]; }
            int s2 = tot;
            #pragma unroll
            for (int off = 1; off < 32; off <<= 1) {
                int o = __shfl_down_sync(0xffffffffu, s2, off);
                if (lane + off < 32) s2 += o;
            }
            int above = s2 - tot;      // count in strictly-higher lanes' buckets
            int foundB = -1, newk = 0, ca = above;
            #pragma unroll
            for (int b = 7; b >= 0; b--) {
                if (foundB < 0 && ca < k && ca + loc[b] >= k) { foundB = lane*8 + b; newk = k - ca; }
                ca += loc[b];
            }
            unsigned bal = __ballot_sync(0xffffffffu, foundB >= 0);
            int srcl = __ffs(bal) - 1;
            foundB = __shfl_sync(0xffffffffu, foundB, srcl);
            k      = __shfl_sync(0xffffffffu, newk,   srcl);
            prefix |= ((unsigned)foundB) << shift;
            __syncwarp();
        }
        // prefix == exact bit pattern of the 256th-largest value (all values >= 0)
        int bh = rrow / NM1;
        int nn = rrow - bh*NM1 + 1;
        float* mout = out_mask + ((size_t)bh*Nn + nn)*Nn;
        const float4* rv4 = (const float4*)rv;
        for (int i = lane; i < 256; i += 32) {
            float4 x = rv4[i];
            float4 mo;
            mo.x = (__float_as_uint(x.x) >= prefix) ? 1.0f : 0.0f;
            mo.y = (__float_as_uint(x.y) >= prefix) ? 1.0f : 0.0f;
            mo.z = (__float_as_uint(x.z) >= prefix) ? 1.0f : 0.0f;
            mo.w = (__float_as_uint(x.w) >= prefix) ? 1.0f : 0.0f;
            ((float4*)mout)[i] = mo;
        }
    }
}

// ---------------- cls rows of the mask ----------------
__global__ void k_cls(float* __restrict__ out_mask) {
    size_t bh = blockIdx.x;
    for (int j = threadIdx.x; j < Nn; j += 256)
        out_mask[bh*Nn*Nn + j] = 1.0f;
}

// ---------------- launch ----------------
extern "C" void kernel_launch(void* const* d_in, const int* in_sizes, int n_in,
                              void* d_out, int out_size) {
    const float* q  = (const float*)d_in[0];
    const float* k  = (const float*)d_in[1];
    const float* wq = (const float*)d_in[2];
    const float* bq = (const float*)d_in[3];
    const float* wk = (const float*)d_in[4];
    const float* bk = (const float*)d_in[5];
    const float* pn = (const float*)d_in[6];
    const float* pb = (const float*)d_in[7];

    float* out       = (float*)d_out;
    float* out_coef  = out;
    float* out_approx = out + (size_t)ROWS_TOT*RNn;
    float* out_mask   = out_approx + (size_t)ROWS_TOT*Nn;

    static int attr_done = 0;
    if (!attr_done) {
        cudaFuncSetAttribute(k_kp2_part, cudaFuncAttributeMaxDynamicSharedMemorySize, 81920);
        cudaFuncSetAttribute(k_spmm_mask, cudaFuncAttributeMaxDynamicSharedMemorySize, 147456);
        attr_done = 1;
    }

    k_basis<<<512, 256>>>(pb);
    k_proj<<<768, 256>>>(q, wq, bq, 0);
    k_proj<<<768, 256>>>(k, wk, bk, 1);
    k_kp2_part<<<dim3(BHn, 8), 256, 81920>>>(pn);
    k_kp2_red<<<1536, 256>>>();
    k_cheap<<<ROWS_TOT/8, 256>>>(out_coef);
    k_spmm_mask<<<ROWS_TOT/32, 512, 147456>>>(out_approx, out_mask);
    k_cls<<<BHn, 256>>>(out_mask);
}

// round 2
// speedup vs baseline: 1.0876x; 1.0876x over previous
#include <cuda_runtime.h>
#include <math.h>
#include <stdint.h>

#define BHn   96
#define Nn    1024
#define Cc    64
#define RCc   32
#define RNn   128
#define NM1   1023
#define ROWS_TOT (BHn*NM1)   /* 98208 */
#define KTOP  16
#define BUDGET 256

// ---------------- scratch ----------------
__device__ __align__(16) float g_qp[BHn*Nn*RCc];
__device__ __align__(16) float g_kp[BHn*Nn*RCc];
__device__ __align__(16) float g_kp2p[8*BHn*RCc*RNn];
__device__ __align__(16) float g_kp2[BHn*RCc*RNn];
__device__ __align__(16) float g_basis[RNn*Nn];
__device__ __align__(16) float g_cval[(size_t)ROWS_TOT*KTOP];
__device__ __align__(16) int   g_cidx[(size_t)ROWS_TOT*KTOP];

// packed f32x2 helpers
__device__ __forceinline__ void fma2(unsigned long long &d, unsigned long long a, unsigned long long b) {
    asm("fma.rn.f32x2 %0, %1, %2, %0;" : "+l"(d) : "l"(a), "l"(b));
}
__device__ __forceinline__ unsigned long long pk2(float x, float y) {
    unsigned long long r; asm("mov.b64 %0, {%1, %2};" : "=l"(r) : "f"(x), "f"(y)); return r;
}
__device__ __forceinline__ void upk2(unsigned long long v, float &x, float &y) {
    asm("mov.b64 {%0, %1}, %2;" : "=f"(x), "=f"(y) : "l"(v));
}

// ---------------- basis = Threshold(|proj_back_n.T|) ----------------
__global__ void k_basis(const float* __restrict__ pb) {
    int i = blockIdx.x*256 + threadIdx.x;
    if (i < RNn*Nn) {
        int j = i >> 7, c = i & 127;
        float v = fabsf(pb[i]);
        g_basis[(size_t)c*Nn + j] = (v > 0.02f) ? v : 0.0f;
    }
}

// ---------------- qp / kp projection ----------------
__global__ void k_proj(const float* __restrict__ x, const float* __restrict__ w,
                       const float* __restrict__ b, int which) {
    float* out = which ? g_kp : g_qp;
    int warp = threadIdx.x >> 5, lane = threadIdx.x & 31;
    int row0 = (blockIdx.x*8 + warp)*16;
    float wr[64];
    #pragma unroll
    for (int c4 = 0; c4 < 16; c4++) {
        float4 t = *(const float4*)(w + lane*64 + c4*4);
        wr[c4*4+0]=t.x; wr[c4*4+1]=t.y; wr[c4*4+2]=t.z; wr[c4*4+3]=t.w;
    }
    float bias = b[lane];
    for (int r = 0; r < 16; r++) {
        int row = row0 + r;
        float qlo = x[(size_t)row*64 + lane];
        float qhi = x[(size_t)row*64 + 32 + lane];
        float acc = 0.0f;
        #pragma unroll
        for (int c = 0; c < 32; c++) acc = fmaf(__shfl_sync(0xffffffffu, qlo, c), wr[c],    acc);
        #pragma unroll
        for (int c = 0; c < 32; c++) acc = fmaf(__shfl_sync(0xffffffffu, qhi, c), wr[32+c], acc);
        out[(size_t)row*32 + lane] = acc + bias;
    }
}

// ---------------- kp2 partial: smem kp tile only, proj via L2 broadcast ----------------
__global__ void k_kp2_part(const float* __restrict__ proj_n) {
    __shared__ float kp_s[128*32];    // 16 KB
    int bh = blockIdx.x, ch = blockIdx.y;
    int n0 = ch*128, tid = threadIdx.x;
    const float4* src = (const float4*)(g_kp + ((size_t)bh*Nn + n0)*32);
    float4* dst = (float4*)kp_s;
    for (int i = tid; i < 1024; i += 256) dst[i] = src[i];
    __syncthreads();
    int rc0 = (tid & 7)*4;
    int rn0 = (tid >> 3)*4;
    float acc[4][4];
    #pragma unroll
    for (int i = 0; i < 4; i++)
        #pragma unroll
        for (int j = 0; j < 4; j++) acc[i][j] = 0.0f;
    const float4* pjp = (const float4*)(proj_n + (size_t)n0*128 + rn0);
    #pragma unroll 4
    for (int n = 0; n < 128; n++) {
        float4 a = *(const float4*)(kp_s + n*32 + rc0);
        float4 p = __ldg(pjp + n*32);      // 128 floats / 4 = 32 float4 per row
        float av[4] = {a.x,a.y,a.z,a.w};
        float pv[4] = {p.x,p.y,p.z,p.w};
        #pragma unroll
        for (int i = 0; i < 4; i++)
            #pragma unroll
            for (int j = 0; j < 4; j++) acc[i][j] = fmaf(av[i], pv[j], acc[i][j]);
    }
    float* outp = g_kp2p + ((size_t)ch*BHn + bh)*4096;
    #pragma unroll
    for (int i = 0; i < 4; i++) {
        float4 o = {acc[i][0], acc[i][1], acc[i][2], acc[i][3]};
        *(float4*)(outp + (rc0+i)*128 + rn0) = o;
    }
}

__global__ void k_kp2_red() {
    int i = blockIdx.x*256 + threadIdx.x;
    if (i < BHn*RCc*RNn) {
        float s = 0.0f;
        #pragma unroll
        for (int ch = 0; ch < 8; ch++) s += g_kp2p[(size_t)ch*BHn*4096 + i];
        g_kp2[i] = s;
    }
}

// ---------------- cheap_attn + softmax + topk16 ----------------
__global__ void k_cheap(float* __restrict__ out_coef) {
    int warp = threadIdx.x >> 5, lane = threadIdx.x & 31;
    int rr = blockIdx.x*8 + warp;
    if (rr >= ROWS_TOT) return;
    int bh = rr / NM1;
    int n  = rr - bh*NM1 + 1;

    float qv = g_qp[((size_t)bh*Nn + n)*32 + lane];
    const float4* kb = (const float4*)(g_kp2 + (size_t)bh*4096);
    float4 acc = {0.f,0.f,0.f,0.f};
    #pragma unroll
    for (int rc = 0; rc < 32; rc++) {
        float a = __shfl_sync(0xffffffffu, qv, rc);
        float4 kv = __ldg(kb + rc*32 + lane);
        acc.x = fmaf(a, kv.x, acc.x);
        acc.y = fmaf(a, kv.y, acc.y);
        acc.z = fmaf(a, kv.z, acc.z);
        acc.w = fmaf(a, kv.w, acc.w);
    }
    const float scale = 0.28867513459481287f;
    float l[4] = {acc.x*scale, acc.y*scale, acc.z*scale, acc.w*scale};

    float m = fmaxf(fmaxf(l[0], l[1]), fmaxf(l[2], l[3]));
    #pragma unroll
    for (int off = 16; off; off >>= 1) m = fmaxf(m, __shfl_xor_sync(0xffffffffu, m, off));
    float e[4], s = 0.0f;
    #pragma unroll
    for (int j = 0; j < 4; j++) { e[j] = expf(l[j] - m); s += e[j]; }
    #pragma unroll
    for (int off = 16; off; off >>= 1) s += __shfl_xor_sync(0xffffffffu, s, off);
    float c[4];
    #pragma unroll
    for (int j = 0; j < 4; j++) c[j] = e[j] / s;

    unsigned rem = 0xFu, sel = 0u;
    float myv = 0.0f; int myi = 0;
    for (int t = 0; t < 16; t++) {
        float bv = -1.0f; int bi = 0x7fffffff;
        #pragma unroll
        for (int j = 0; j < 4; j++) {
            if (rem & (1u << j)) {
                float v = c[j]; int idx = lane*4 + j;
                if (v > bv || (v == bv && idx < bi)) { bv = v; bi = idx; }
            }
        }
        #pragma unroll
        for (int off = 16; off; off >>= 1) {
            float ov = __shfl_xor_sync(0xffffffffu, bv, off);
            int   oi = __shfl_xor_sync(0xffffffffu, bi, off);
            if (ov > bv || (ov == bv && oi < bi)) { bv = ov; bi = oi; }
        }
        if ((bi >> 2) == lane) { rem &= ~(1u << (bi & 3)); sel |= (1u << (bi & 3)); }
        if (lane == t) { myv = bv; myi = bi; }
    }
    int rank = 0;
    #pragma unroll
    for (int u = 0; u < 16; u++) {
        int oi = __shfl_sync(0xffffffffu, myi, u);
        if (u != lane && oi < myi) rank++;
    }
    if (lane < 16) {
        g_cval[(size_t)rr*16 + rank] = myv;
        g_cidx[(size_t)rr*16 + rank] = myi;
    }
    float4 o;
    o.x = (sel & 1u) ? c[0] : 0.0f;
    o.y = (sel & 2u) ? c[1] : 0.0f;
    o.z = (sel & 4u) ? c[2] : 0.0f;
    o.w = (sel & 8u) ? c[3] : 0.0f;
    *(float4*)(out_coef + (size_t)rr*128 + lane*4) = o;
}

// ---------------- fused sparse SpMM + top-256 mask: warp-per-row, register rows ----------------
__global__ __launch_bounds__(256) void k_spmm_mask(float* __restrict__ out_approx,
                                                   float* __restrict__ out_mask) {
    __shared__ int hist[8][256];
    int warp = threadIdx.x >> 5, lane = threadIdx.x & 31;
    int rr = blockIdx.x*8 + warp;

    const float* cvp = g_cval + (size_t)rr*16;
    const int*   cip = g_cidx + (size_t)rr*16;

    unsigned long long acc[16];
    #pragma unroll
    for (int j = 0; j < 16; j++) acc[j] = 0ULL;

    #pragma unroll 4
    for (int t = 0; t < 16; t++) {
        float v = __ldg(cvp + t);
        int   ci = __ldg(cip + t);
        unsigned long long vv = pk2(v, v);
        const float4* bp = (const float4*)g_basis + (size_t)ci*256;
        #pragma unroll
        for (int j = 0; j < 8; j++) {
            float4 x = __ldg(bp + j*32 + lane);
            fma2(acc[2*j],   pk2(x.x, x.y), vv);
            fma2(acc[2*j+1], pk2(x.z, x.w), vv);
        }
    }

    // write approx_attn (streaming stores — keep basis in L2)
    float* outp = out_approx + (size_t)rr*1024;
    #pragma unroll
    for (int j = 0; j < 8; j++) {
        float4 o;
        upk2(acc[2*j],   o.x, o.y);
        upk2(acc[2*j+1], o.z, o.w);
        __stcs((float4*)outp + j*32 + lane, o);
    }

    // exact top-256 threshold: 4-pass 8-bit radix over positive-float bit patterns
    int* h = hist[warp];
    unsigned prefix = 0u; int k = BUDGET;
    #pragma unroll
    for (int pass = 0; pass < 4; pass++) {
        int shift = 24 - pass*8;
        for (int i = lane; i < 256; i += 32) h[i] = 0;
        __syncwarp();
        #pragma unroll
        for (int i = 0; i < 32; i++) {
            unsigned u = (unsigned)(acc[i >> 1] >> ((i & 1)*32));
            bool match = (pass == 0) || ((u >> (shift + 8)) == (prefix >> (shift + 8)));
            if (match) atomicAdd(&h[(u >> shift) & 255u], 1);
        }
        __syncwarp();
        int loc[8]; int tot = 0;
        #pragma unroll
        for (int b = 0; b < 8; b++) { loc[b] = h[lane*8 + b]; tot += loc[b]; }
        int s2 = tot;
        #pragma unroll
        for (int off = 1; off < 32; off <<= 1) {
            int o = __shfl_down_sync(0xffffffffu, s2, off);
            if (lane + off < 32) s2 += o;
        }
        int above = s2 - tot;
        int foundB = -1, newk = 0, ca = above;
        #pragma unroll
        for (int b = 7; b >= 0; b--) {
            if (foundB < 0 && ca < k && ca + loc[b] >= k) { foundB = lane*8 + b; newk = k - ca; }
            ca += loc[b];
        }
        unsigned bal = __ballot_sync(0xffffffffu, foundB >= 0);
        int srcl = __ffs(bal) - 1;
        foundB = __shfl_sync(0xffffffffu, foundB, srcl);
        k      = __shfl_sync(0xffffffffu, newk,   srcl);
        prefix |= ((unsigned)foundB) << shift;
        __syncwarp();
    }

    // write mask row (threshold = exact bits of 256th-largest)
    int bh = rr / NM1;
    int nn = rr - bh*NM1 + 1;
    float* mout = out_mask + ((size_t)bh*Nn + nn)*Nn;
    #pragma unroll
    for (int j = 0; j < 8; j++) {
        unsigned u0 = (unsigned)(acc[2*j]);
        unsigned u1 = (unsigned)(acc[2*j] >> 32);
        unsigned u2 = (unsigned)(acc[2*j+1]);
        unsigned u3 = (unsigned)(acc[2*j+1] >> 32);
        float4 mo;
        mo.x = (u0 >= prefix) ? 1.0f : 0.0f;
        mo.y = (u1 >= prefix) ? 1.0f : 0.0f;
        mo.z = (u2 >= prefix) ? 1.0f : 0.0f;
        mo.w = (u3 >= prefix) ? 1.0f : 0.0f;
        __stcs((float4*)mout + j*32 + lane, mo);
    }
}

// ---------------- cls rows ----------------
__global__ void k_cls(float* __restrict__ out_mask) {
    size_t bh = blockIdx.x;
    for (int j = threadIdx.x; j < Nn; j += 256)
        out_mask[bh*Nn*Nn + j] = 1.0f;
}

// ---------------- launch ----------------
extern "C" void kernel_launch(void* const* d_in, const int* in_sizes, int n_in,
                              void* d_out, int out_size) {
    const float* q  = (const float*)d_in[0];
    const float* k  = (const float*)d_in[1];
    const float* wq = (const float*)d_in[2];
    const float* bq = (const float*)d_in[3];
    const float* wk = (const float*)d_in[4];
    const float* bk = (const float*)d_in[5];
    const float* pn = (const float*)d_in[6];
    const float* pb = (const float*)d_in[7];

    float* out        = (float*)d_out;
    float* out_coef   = out;
    float* out_approx = out + (size_t)ROWS_TOT*RNn;
    float* out_mask   = out_approx + (size_t)ROWS_TOT*Nn;

    k_basis<<<512, 256>>>(pb);
    k_proj<<<768, 256>>>(q, wq, bq, 0);
    k_proj<<<768, 256>>>(k, wk, bk, 1);
    k_kp2_part<<<dim3(BHn, 8), 256>>>(pn);
    k_kp2_red<<<1536, 256>>>();
    k_cheap<<<ROWS_TOT/8, 256>>>(out_coef);
    k_spmm_mask<<<ROWS_TOT/8, 256>>>(out_approx, out_mask);
    k_cls<<<BHn, 256>>>(out_mask);
}